// round 9
// baseline (speedup 1.0000x reference)
#include <cuda_runtime.h>
#include <cuda_bf16.h>
#include <stdint.h>

#define NB 64
#define TT 25
#define LL 196
#define VOC 32000
#define EMB 512
#define PROJD 1024
#define DEC 1024
#define NSTEP 24

// ---------------- device state (no allocations allowed) ----------------
// Weights stored bf16 with GATE-PERMUTED rows: permuted row p = jblk*32 + q*8 + jr
// (jblk = j>>3, jr = j&7, q = gate) <-> original row q*1024 + j. One 32-row tile
// holds all 4 gates for 8 consecutive j -> gate nonlinearity fusable into GEMM epilogue.
__device__ __nv_bfloat16 d_wcat0[4096 * 2560];      // layer0 [Wih | Whh]
__device__ __nv_bfloat16 d_wcat12[2][4096 * 2048];  // layers 1,2
__device__ __nv_bfloat16 d_pw[(long)VOC * DEC];     // out_W bf16
__device__ __nv_bfloat16 d_kbf[(long)NB * LL * DEC];
__device__ __nv_bfloat16 d_vbf[(long)NB * LL * PROJD];
__device__ float d_bsum[3][4096];                   // b_ih + b_hh per layer (original order)
__device__ __nv_bfloat16 d_xc0[NB * 2560];          // [emb | ctx | h0]
__device__ __nv_bfloat16 d_xc1[NB * 2048];          // [h0_new | h1]
__device__ __nv_bfloat16 d_xc2[NB * 2048];          // [h1_new | h2]
__device__ __nv_bfloat16 d_hlastb[(long)NSTEP * NB * DEC];
__device__ float d_cbuf[3][NB * DEC];
__device__ float d_h2[NB * DEC];
__device__ float d_att[NB * LL];

__device__ __forceinline__ float sigmf(float x) { return 1.0f / (1.0f + expf(-x)); }

__device__ __forceinline__ uint32_t smem_u32(const void* p) {
    uint32_t a;
    asm("{ .reg .u64 t; cvta.to.shared.u64 t, %1; cvt.u32.u64 %0, t; }" : "=r"(a) : "l"(p));
    return a;
}
#define CPA16(d, s) asm volatile("cp.async.ca.shared.global [%0], [%1], 16;" :: "r"(d), "l"(s))
#define CP_COMMIT() asm volatile("cp.async.commit_group;" ::: "memory")
#define CP_WAIT2() asm volatile("cp.async.wait_group 2;" ::: "memory")
#define CP_WAIT1() asm volatile("cp.async.wait_group 1;" ::: "memory")
#define CP_WAIT0() asm volatile("cp.async.wait_group 0;" ::: "memory")

// C[16x8] += A[16x16] * B[16x8], bf16 inputs, fp32 accum
__device__ __forceinline__ void mma_bf16(float* c, const uint32_t* a, uint32_t b0, uint32_t b1) {
    asm volatile(
        "mma.sync.aligned.m16n8k16.row.col.f32.bf16.bf16.f32 "
        "{%0,%1,%2,%3}, {%4,%5,%6,%7}, {%8,%9}, {%0,%1,%2,%3};"
        : "+f"(c[0]), "+f"(c[1]), "+f"(c[2]), "+f"(c[3])
        : "r"(a[0]), "r"(a[1]), "r"(a[2]), "r"(a[3]), "r"(b0), "r"(b1));
}

// ---------------- single fused conversion kernel ----------------
__global__ void conv_all(const float4* __restrict__ Wih0, const float4* __restrict__ Whh0,
                         const float4* __restrict__ Wihr, const float4* __restrict__ Whhr,
                         const float4* __restrict__ outW, const float4* __restrict__ keys,
                         const float4* __restrict__ values,
                         const float4* __restrict__ bih0, const float4* __restrict__ bhh0,
                         const float4* __restrict__ bihr, const float4* __restrict__ bhhr) {
    const long N0 = 2621440L;            // w0: 4096 x 640 granules
    const long N1 = N0 + 2097152L;       // w1: 4096 x 512
    const long N2 = N1 + 2097152L;       // w2
    const long N3 = N2 + 8192000L;       // pw: 32000 x 256
    const long N4 = N3 + 3211264L;       // keys
    const long N5 = N4 + 3211264L;       // values
    const long N6 = N5 + 3072L;          // biases (float4 granules)
    for (long i = (long)blockIdx.x * blockDim.x + threadIdx.x; i < N6;
         i += (long)gridDim.x * blockDim.x) {
        float4 v;
        __nv_bfloat16* dst;
        if (i < N0) {
            long o = i;
            int p = (int)(o / 640), k4 = (int)(o - (long)p * 640);
            int r = ((p >> 3) & 3) * 1024 + (p >> 5) * 8 + (p & 7);
            v = (k4 < 384) ? Wih0[(long)r * 384 + k4] : Whh0[(long)r * 256 + (k4 - 384)];
            dst = d_wcat0 + o * 4;
        } else if (i < N2) {
            int lay = (i < N1) ? 0 : 1;
            long o = i - (lay ? N1 : N0);
            int p = (int)(o / 512), k4 = (int)(o - (long)p * 512);
            int r = ((p >> 3) & 3) * 1024 + (p >> 5) * 8 + (p & 7) + lay * 4096;
            v = (k4 < 256) ? Wihr[(long)r * 256 + k4] : Whhr[(long)r * 256 + (k4 - 256)];
            dst = d_wcat12[lay] + o * 4;
        } else if (i < N3) {
            long o = i - N2; v = outW[o]; dst = d_pw + o * 4;
        } else if (i < N4) {
            long o = i - N3; v = keys[o]; dst = d_kbf + o * 4;
        } else if (i < N5) {
            long o = i - N4; v = values[o]; dst = d_vbf + o * 4;
        } else {
            long o = i - N5;
            int lay = (int)(o >> 10), r4 = (int)(o & 1023);
            float4 a, b;
            if (lay == 0)      { a = bih0[r4];        b = bhh0[r4]; }
            else if (lay == 1) { a = bihr[r4];        b = bhhr[r4]; }
            else               { a = bihr[1024 + r4]; b = bhhr[1024 + r4]; }
            *(float4*)&d_bsum[lay][r4 * 4] =
                make_float4(a.x + b.x, a.y + b.y, a.z + b.z, a.w + b.w);
            continue;
        }
        __nv_bfloat162* d2 = (__nv_bfloat162*)dst;
        d2[0] = __nv_bfloat162(__float2bfloat16_rn(v.x), __float2bfloat16_rn(v.y));
        d2[1] = __nv_bfloat162(__float2bfloat16_rn(v.z), __float2bfloat16_rn(v.w));
    }
}

// ---------------- init ----------------
__global__ void init_state(const float* __restrict__ ih, const float* __restrict__ ic,
                           const float* __restrict__ ictx, const float* __restrict__ emb) {
    int idx = blockIdx.x * blockDim.x + threadIdx.x;
    if (idx >= NB * 2560) return;
    int n = idx / 2560, j = idx % 2560;
    __nv_bfloat16 bv;
    if (j < 512) bv = __float2bfloat16_rn(emb[512 + j]);  // <start> = token 1
    else if (j < 1536) bv = __float2bfloat16_rn(ictx[j - 512]);
    else bv = __float2bfloat16_rn(ih[j - 1536]);
    d_xc0[idx] = bv;
    if (j < 1024) {
        d_xc1[n * 2048 + 1024 + j] = __float2bfloat16_rn(ih[1024 + j]);
        d_xc2[n * 2048 + 1024 + j] = __float2bfloat16_rn(ih[2048 + j]);
        d_cbuf[0][n * 1024 + j] = ic[j];
        d_cbuf[1][n * 1024 + j] = ic[1024 + j];
        d_cbuf[2][n * 1024 + j] = ic[2048 + j];
        d_h2[n * 1024 + j] = ih[2048 + j];
    }
}

__global__ void out0_kernel(float* __restrict__ out) {
    int idx = blockIdx.x * blockDim.x + threadIdx.x;
    if (idx < NB * VOC) {
        int n = idx / VOC, v = idx % VOC;
        out[(long)n * TT * VOC + v] = (v == 1) ? 10000.0f : 0.0f;
    }
}

// ---------------- fused LSTM: GEMM (full K) + gate nonlinearity in epilogue ----------------
// grid 128 (jblk), 128 threads. CTA tile: 64 batch x 32 permuted W rows (= 8 j x 4 gates).
// stage: X 64 rows x 32 halves (stride 80B) = 5120B, W 32 rows = 2560B.
#define LSTG 7680
#define LS_SMEM (4 * LSTG)

template <int LAYER>
__device__ __forceinline__ void lstm_ld(char* smem, int stg, int k0, int tid) {
    uint32_t st = smem_u32(smem) + stg * LSTG;
    const __nv_bfloat16* Xc = (LAYER == 0) ? d_xc0 : (LAYER == 1) ? d_xc1 : d_xc2;
    const __nv_bfloat16* Wc = (LAYER == 0) ? d_wcat0 : d_wcat12[LAYER - 1];
    const int Ktot = (LAYER == 0) ? 2560 : 2048;
#pragma unroll
    for (int i = 0; i < 2; i++) {
        int gI = tid + i * 128;
        int row = gI >> 2, c = gI & 3;
        CPA16(st + row * 80 + c * 16, Xc + (long)row * Ktot + k0 + c * 8);
    }
    {
        int row = tid >> 2, c = tid & 3;
        CPA16(st + 5120 + row * 80 + c * 16,
              Wc + ((long)blockIdx.x * 32 + row) * Ktot + k0 + c * 8);
    }
}

template <int LAYER>
__global__ __launch_bounds__(128) void lstm_fused(int step) {
    extern __shared__ char smem[];
    const int Ktot = (LAYER == 0) ? 2560 : 2048;
    const int NCH = Ktot / 32;
    const int tid = threadIdx.x;
    const int w = tid >> 5, lane = tid & 31, g = lane >> 2, tig = lane & 3;
    const int bn = blockIdx.x;

    float acc[4][4] = {};

    lstm_ld<LAYER>(smem, 0, 0, tid);  CP_COMMIT();
    lstm_ld<LAYER>(smem, 1, 32, tid); CP_COMMIT();
    lstm_ld<LAYER>(smem, 2, 64, tid); CP_COMMIT();

    for (int c = 0; c < NCH; c++) {
        if (c + 2 < NCH) CP_WAIT2();
        else if (c + 1 < NCH) CP_WAIT1();
        else CP_WAIT0();
        __syncthreads();
        if (c + 3 < NCH) { lstm_ld<LAYER>(smem, (c + 3) & 3, (c + 3) * 32, tid); CP_COMMIT(); }
        const uint32_t* Xu = (const uint32_t*)(smem + (c & 3) * LSTG);
        const uint32_t* Wu = (const uint32_t*)(smem + (c & 3) * LSTG + 5120);
        int m0g = (w * 16 + g) * 20;
#pragma unroll
        for (int ks = 0; ks < 2; ks++) {
            int k8 = ks * 8;
            uint32_t a[4];
            a[0] = Xu[m0g + k8 + tig];
            a[1] = Xu[m0g + 160 + k8 + tig];
            a[2] = Xu[m0g + k8 + tig + 4];
            a[3] = Xu[m0g + 160 + k8 + tig + 4];
#pragma unroll
            for (int nf = 0; nf < 4; nf++) {
                int nr = (nf * 8 + g) * 20;
                mma_bf16(acc[nf], a, Wu[nr + k8 + tig], Wu[nr + k8 + tig + 4]);
            }
        }
    }

    // Epilogue: thread holds all 4 gates (nf = q) for j = bn*8 + tig*2 + {0,1},
    // batch rows m = w*16+g and m+8. Apply LSTM cell directly.
    int m = w * 16 + g;
#pragma unroll
    for (int half = 0; half < 2; half++) {
        int mm = m + half * 8;
#pragma unroll
        for (int pair = 0; pair < 2; pair++) {
            int j = bn * 8 + tig * 2 + pair;
            int sel = half * 2 + pair;
            float iv = acc[0][sel] + d_bsum[LAYER][j];
            float fv = acc[1][sel] + d_bsum[LAYER][1024 + j];
            float gv = acc[2][sel] + d_bsum[LAYER][2048 + j];
            float ov = acc[3][sel] + d_bsum[LAYER][3072 + j];
            float c2 = sigmf(fv) * d_cbuf[LAYER][mm * 1024 + j] + sigmf(iv) * tanhf(gv);
            float h2 = sigmf(ov) * tanhf(c2);
            d_cbuf[LAYER][mm * 1024 + j] = c2;
            __nv_bfloat16 hb = __float2bfloat16_rn(h2);
            if (LAYER == 0) {
                d_xc1[mm * 2048 + j] = hb;
                d_xc0[mm * 2560 + 1536 + j] = hb;
            } else if (LAYER == 1) {
                d_xc2[mm * 2048 + j] = hb;
                d_xc1[mm * 2048 + 1024 + j] = hb;
            } else {
                d_xc2[mm * 2048 + 1024 + j] = hb;
                d_h2[mm * 1024 + j] = h2;
                d_hlastb[((long)step * NB + mm) * 1024 + j] = hb;
            }
        }
    }
}

// ---------------- attention part 1: energy = keys . h2 (bf16 keys) ----------------
__global__ void energy_kernel() {
    int n = blockIdx.x;
    int l = blockIdx.y * 8 + (threadIdx.x >> 5);
    int lane = threadIdx.x & 31;
    __shared__ float hs[DEC];
    for (int k = threadIdx.x; k < DEC; k += 256) hs[k] = d_h2[n * DEC + k];
    __syncthreads();
    if (l >= LL) return;
    const __nv_bfloat162* kr = (const __nv_bfloat162*)(d_kbf + ((long)n * LL + l) * DEC);
    float s = 0.f;
#pragma unroll
    for (int i = 0; i < 16; i++) {
        __nv_bfloat162 v = kr[lane + i * 32];
        int k2 = (lane + i * 32) * 2;
        s += __bfloat162float(v.x) * hs[k2] + __bfloat162float(v.y) * hs[k2 + 1];
    }
#pragma unroll
    for (int o = 16; o; o >>= 1) s += __shfl_xor_sync(0xffffffffu, s, o);
    if (lane == 0) d_att[n * LL + l] = s;
}

// ---------------- attention part 2: softmax + ctx + x0 build for next step ----------------
__global__ void softctx_kernel(const int* __restrict__ captions, const float* __restrict__ emb,
                               int next_step) {
    int n = blockIdx.x;
    int tid = threadIdx.x;
    int wid = tid >> 5, lane = tid & 31;
    __shared__ float e[LL];
    __shared__ float red[8], red2[8];
    float v = (tid < LL) ? d_att[n * LL + tid] : -3.4e38f;
    float m = v;
#pragma unroll
    for (int o = 16; o; o >>= 1) m = fmaxf(m, __shfl_xor_sync(0xffffffffu, m, o));
    if (lane == 0) red[wid] = m;
    __syncthreads();
    if (tid < 8) {
        float mm = red[tid];
#pragma unroll
        for (int o = 4; o; o >>= 1) mm = fmaxf(mm, __shfl_xor_sync(0xffu, mm, o));
        if (tid == 0) red[0] = mm;
    }
    __syncthreads();
    float gm = red[0];
    float ex = (tid < LL) ? expf(v - gm) : 0.f;
    float s = ex;
#pragma unroll
    for (int o = 16; o; o >>= 1) s += __shfl_xor_sync(0xffffffffu, s, o);
    if (lane == 0) red2[wid] = s;
    __syncthreads();
    if (tid < 8) {
        float ss = red2[tid];
#pragma unroll
        for (int o = 4; o; o >>= 1) ss += __shfl_xor_sync(0xffu, ss, o);
        if (tid == 0) red2[0] = ss;
    }
    __syncthreads();
    if (tid < LL) e[tid] = ex / red2[0];
    __syncthreads();
    int col = blockIdx.y * 256 + tid;
    const __nv_bfloat16* vp = d_vbf + (long)n * LL * PROJD + col;
    float acc = 0.f;
#pragma unroll 4
    for (int l = 0; l < LL; l++) acc += e[l] * __bfloat162float(vp[(long)l * PROJD]);
    d_xc0[n * 2560 + 512 + col] = __float2bfloat16_rn(acc);
    if (blockIdx.y == 0) {
        int tok = captions[n * TT + next_step];
        for (int k = tid; k < EMB; k += 256)
            d_xc0[n * 2560 + k] = __float2bfloat16_rn(emb[(long)tok * EMB + k]);
    }
}

// ---------------- projection (bf16 mma, 4-stage): out = hlast @ out_W^T ----------------
#define PSTAGE 20480
#define PJ_SMEM (4 * PSTAGE)

__device__ __forceinline__ void proj_ld(uint32_t st, int bm, int bn, int k0, int tid) {
#pragma unroll
    for (int i = 0; i < 2; i++) {
        int gI = tid + i * 256;
        int row = gI >> 2, c = gI & 3;
        CPA16(st + row * 80 + c * 16, d_hlastb + (long)(bm * 128 + row) * DEC + k0 + c * 8);
    }
#pragma unroll
    for (int i = 0; i < 2; i++) {
        int gI = tid + i * 256;
        int row = gI >> 2, c = gI & 3;
        CPA16(st + 10240 + row * 80 + c * 16, d_pw + (long)(bn * 128 + row) * DEC + k0 + c * 8);
    }
}

__global__ __launch_bounds__(256) void proj_mma(const float* __restrict__ bias,
                                                float* __restrict__ out) {
    extern __shared__ char smem[];
    uint32_t sb = smem_u32(smem);
    const int tid = threadIdx.x;
    const int w = tid >> 5, lane = tid & 31, g = lane >> 2, tig = lane & 3;
    const int wm = w >> 2, wn = w & 3;
    const int bm = blockIdx.x, bn = blockIdx.y;

    float acc[4][4][4] = {};

    proj_ld(sb, bm, bn, 0, tid);  CP_COMMIT();
    proj_ld(sb + PSTAGE, bm, bn, 32, tid); CP_COMMIT();
    proj_ld(sb + 2 * PSTAGE, bm, bn, 64, tid); CP_COMMIT();

    for (int c = 0; c < 32; c++) {
        if (c + 2 < 32) CP_WAIT2();
        else if (c + 1 < 32) CP_WAIT1();
        else CP_WAIT0();
        __syncthreads();
        if (c + 3 < 32) { proj_ld(sb + ((c + 3) & 3) * PSTAGE, bm, bn, (c + 3) * 32, tid); CP_COMMIT(); }
        const uint32_t* Au = (const uint32_t*)(smem + (c & 3) * PSTAGE);
        const uint32_t* Bu = (const uint32_t*)(smem + (c & 3) * PSTAGE + 10240);
#pragma unroll
        for (int ks = 0; ks < 2; ks++) {
            int k8 = ks * 8;
            uint32_t a[4][4];
#pragma unroll
            for (int mi = 0; mi < 4; mi++) {
                int r = (wm * 64 + mi * 16 + g) * 20;
                a[mi][0] = Au[r + k8 + tig];
                a[mi][1] = Au[r + 160 + k8 + tig];
                a[mi][2] = Au[r + k8 + tig + 4];
                a[mi][3] = Au[r + 160 + k8 + tig + 4];
            }
#pragma unroll
            for (int nj = 0; nj < 4; nj++) {
                int nr = (wn * 32 + nj * 8 + g) * 20;
                uint32_t b0 = Bu[nr + k8 + tig], b1 = Bu[nr + k8 + tig + 4];
#pragma unroll
                for (int mi = 0; mi < 4; mi++) mma_bf16(acc[mi][nj], a[mi], b0, b1);
            }
        }
    }

#pragma unroll
    for (int mi = 0; mi < 4; mi++) {
#pragma unroll
        for (int nj = 0; nj < 4; nj++) {
            int m0 = bm * 128 + wm * 64 + mi * 16 + g;
            int vv = bn * 128 + wn * 32 + nj * 8 + tig * 2;
            float b0 = bias[vv], b1 = bias[vv + 1];
            {
                int step = m0 >> 6, nn = m0 & 63;
                *(float2*)(out + ((long)nn * TT + step + 1) * VOC + vv) =
                    make_float2(acc[mi][nj][0] + b0, acc[mi][nj][1] + b1);
            }
            {
                int m1 = m0 + 8;
                int step = m1 >> 6, nn = m1 & 63;
                *(float2*)(out + ((long)nn * TT + step + 1) * VOC + vv) =
                    make_float2(acc[mi][nj][2] + b0, acc[mi][nj][3] + b1);
            }
        }
    }
}

// ---------------- launch ----------------
extern "C" void kernel_launch(void* const* d_in, const int* in_sizes, int n_in,
                              void* d_out, int out_size) {
    int sh = (n_in >= 19) ? 0 : 1;
    const float* keys     = (const float*)d_in[0];
    const float* values   = (const float*)d_in[1];
    const int*   captions = (const int*)d_in[3];
    const float* emb      = (const float*)d_in[5 - sh];
    const float* W_ih0    = (const float*)d_in[6 - sh];
    const float* W_hh0    = (const float*)d_in[7 - sh];
    const float* b_ih0    = (const float*)d_in[8 - sh];
    const float* b_hh0    = (const float*)d_in[9 - sh];
    const float* W_ih_r   = (const float*)d_in[10 - sh];
    const float* W_hh_r   = (const float*)d_in[11 - sh];
    const float* b_ih_r   = (const float*)d_in[12 - sh];
    const float* b_hh_r   = (const float*)d_in[13 - sh];
    const float* out_W    = (const float*)d_in[14 - sh];
    const float* out_b    = (const float*)d_in[15 - sh];
    const float* init_h   = (const float*)d_in[16 - sh];
    const float* init_c   = (const float*)d_in[17 - sh];
    const float* init_ctx = (const float*)d_in[18 - sh];
    float* out = (float*)d_out;

    cudaFuncSetAttribute(lstm_fused<0>, cudaFuncAttributeMaxDynamicSharedMemorySize, LS_SMEM);
    cudaFuncSetAttribute(lstm_fused<1>, cudaFuncAttributeMaxDynamicSharedMemorySize, LS_SMEM);
    cudaFuncSetAttribute(lstm_fused<2>, cudaFuncAttributeMaxDynamicSharedMemorySize, LS_SMEM);
    cudaFuncSetAttribute(proj_mma, cudaFuncAttributeMaxDynamicSharedMemorySize, PJ_SMEM);

    conv_all<<<2048, 256>>>((const float4*)W_ih0, (const float4*)W_hh0,
                            (const float4*)W_ih_r, (const float4*)W_hh_r,
                            (const float4*)out_W, (const float4*)keys, (const float4*)values,
                            (const float4*)b_ih0, (const float4*)b_hh0,
                            (const float4*)b_ih_r, (const float4*)b_hh_r);

    init_state<<<640, 256>>>(init_h, init_c, init_ctx, emb);
    out0_kernel<<<(NB * VOC + 255) / 256, 256>>>(out);

    for (int s = 0; s < NSTEP; s++) {
        lstm_fused<0><<<128, 128, LS_SMEM>>>(s);
        lstm_fused<1><<<128, 128, LS_SMEM>>>(s);
        lstm_fused<2><<<128, 128, LS_SMEM>>>(s);
        energy_kernel<<<dim3(64, 25), 256>>>();
        softctx_kernel<<<dim3(64, 4), 256>>>(captions, emb, s + 1);
    }

    proj_mma<<<dim3(12, 250), 256, PJ_SMEM>>>(out_b, out);
}

// round 10
// speedup vs baseline: 1.1961x; 1.1961x over previous
#include <cuda_runtime.h>
#include <cuda_bf16.h>
#include <stdint.h>

#define NB 64
#define TT 25
#define LL 196
#define VOC 32000
#define EMB 512
#define PROJD 1024
#define DEC 1024
#define NSTEP 24

// ---------------- device state (no allocations allowed) ----------------
// Weights bf16, GATE-PERMUTED rows: permuted row p = jblk*32 + jr*4 + q
// (j = jblk*8+jr, gate q in {i,f,g,o}) <-> original row q*1024 + j.
// A 32-row tile holds all 4 gates of 8 consecutive j -> gate fusion in epilogue.
__device__ __nv_bfloat16 d_wcat0[4096 * 2560];      // layer0 [Wih | Whh]
__device__ __nv_bfloat16 d_wcat12[2][4096 * 2048];  // layers 1,2
__device__ __nv_bfloat16 d_pw[(long)VOC * DEC];     // out_W bf16
__device__ __nv_bfloat16 d_kbf[(long)NB * LL * DEC];
__device__ __nv_bfloat16 d_vbf[(long)NB * LL * PROJD];
__device__ float d_bsum[3][4096];                   // b_ih + b_hh (original order)
__device__ __nv_bfloat16 d_xc0[NB * 2560];          // [emb | ctx | h0]
__device__ __nv_bfloat16 d_xc1[NB * 2048];          // [h0_new | h1]
__device__ __nv_bfloat16 d_xc2[NB * 2048];          // [h1_new | h2]
__device__ __nv_bfloat16 d_hlastb[(long)NSTEP * NB * DEC];
__device__ float d_cbuf[3][NB * DEC];
__device__ float d_h2[NB * DEC];
__device__ float d_att[NB * LL];

__device__ __forceinline__ float sigmf(float x) { return 1.0f / (1.0f + expf(-x)); }

__device__ __forceinline__ uint32_t smem_u32(const void* p) {
    uint32_t a;
    asm("{ .reg .u64 t; cvta.to.shared.u64 t, %1; cvt.u32.u64 %0, t; }" : "=r"(a) : "l"(p));
    return a;
}
#define CPA16(d, s) asm volatile("cp.async.ca.shared.global [%0], [%1], 16;" :: "r"(d), "l"(s))
#define CP_COMMIT() asm volatile("cp.async.commit_group;" ::: "memory")
#define CP_WAIT3() asm volatile("cp.async.wait_group 3;" ::: "memory")
#define CP_WAIT2() asm volatile("cp.async.wait_group 2;" ::: "memory")
#define CP_WAIT1() asm volatile("cp.async.wait_group 1;" ::: "memory")
#define CP_WAIT0() asm volatile("cp.async.wait_group 0;" ::: "memory")

// C[16x8] += A[16x16] * B[16x8], bf16 inputs, fp32 accum
__device__ __forceinline__ void mma_bf16(float* c, const uint32_t* a, uint32_t b0, uint32_t b1) {
    asm volatile(
        "mma.sync.aligned.m16n8k16.row.col.f32.bf16.bf16.f32 "
        "{%0,%1,%2,%3}, {%4,%5,%6,%7}, {%8,%9}, {%0,%1,%2,%3};"
        : "+f"(c[0]), "+f"(c[1]), "+f"(c[2]), "+f"(c[3])
        : "r"(a[0]), "r"(a[1]), "r"(a[2]), "r"(a[3]), "r"(b0), "r"(b1));
}

// ---------------- single fused conversion kernel ----------------
__global__ void conv_all(const float4* __restrict__ Wih0, const float4* __restrict__ Whh0,
                         const float4* __restrict__ Wihr, const float4* __restrict__ Whhr,
                         const float4* __restrict__ outW, const float4* __restrict__ keys,
                         const float4* __restrict__ values,
                         const float4* __restrict__ bih0, const float4* __restrict__ bhh0,
                         const float4* __restrict__ bihr, const float4* __restrict__ bhhr) {
    const long N0 = 2621440L;            // w0: 4096 x 640 granules
    const long N1 = N0 + 2097152L;       // w1
    const long N2 = N1 + 2097152L;       // w2
    const long N3 = N2 + 8192000L;       // pw
    const long N4 = N3 + 3211264L;       // keys
    const long N5 = N4 + 3211264L;       // values
    const long N6 = N5 + 3072L;          // biases
    for (long i = (long)blockIdx.x * blockDim.x + threadIdx.x; i < N6;
         i += (long)gridDim.x * blockDim.x) {
        float4 v;
        __nv_bfloat16* dst;
        if (i < N0) {
            long o = i;
            int p = (int)(o / 640), k4 = (int)(o - (long)p * 640);
            int r = (p & 3) * 1024 + (p >> 5) * 8 + ((p >> 2) & 7);
            v = (k4 < 384) ? Wih0[(long)r * 384 + k4] : Whh0[(long)r * 256 + (k4 - 384)];
            dst = d_wcat0 + o * 4;
        } else if (i < N2) {
            int lay = (i < N1) ? 0 : 1;
            long o = i - (lay ? N1 : N0);
            int p = (int)(o / 512), k4 = (int)(o - (long)p * 512);
            int r = (p & 3) * 1024 + (p >> 5) * 8 + ((p >> 2) & 7) + lay * 4096;
            v = (k4 < 256) ? Wihr[(long)r * 256 + k4] : Whhr[(long)r * 256 + (k4 - 256)];
            dst = d_wcat12[lay] + o * 4;
        } else if (i < N3) {
            long o = i - N2; v = outW[o]; dst = d_pw + o * 4;
        } else if (i < N4) {
            long o = i - N3; v = keys[o]; dst = d_kbf + o * 4;
        } else if (i < N5) {
            long o = i - N4; v = values[o]; dst = d_vbf + o * 4;
        } else {
            long o = i - N5;
            int lay = (int)(o >> 10), r4 = (int)(o & 1023);
            float4 a, b;
            if (lay == 0)      { a = bih0[r4];        b = bhh0[r4]; }
            else if (lay == 1) { a = bihr[r4];        b = bhhr[r4]; }
            else               { a = bihr[1024 + r4]; b = bhhr[1024 + r4]; }
            *(float4*)&d_bsum[lay][r4 * 4] =
                make_float4(a.x + b.x, a.y + b.y, a.z + b.z, a.w + b.w);
            continue;
        }
        __nv_bfloat162* d2 = (__nv_bfloat162*)dst;
        d2[0] = __nv_bfloat162(__float2bfloat16_rn(v.x), __float2bfloat16_rn(v.y));
        d2[1] = __nv_bfloat162(__float2bfloat16_rn(v.z), __float2bfloat16_rn(v.w));
    }
}

// ---------------- init ----------------
__global__ void init_state(const float* __restrict__ ih, const float* __restrict__ ic,
                           const float* __restrict__ ictx, const float* __restrict__ emb) {
    int idx = blockIdx.x * blockDim.x + threadIdx.x;
    if (idx >= NB * 2560) return;
    int n = idx / 2560, j = idx % 2560;
    __nv_bfloat16 bv;
    if (j < 512) bv = __float2bfloat16_rn(emb[512 + j]);  // <start> = token 1
    else if (j < 1536) bv = __float2bfloat16_rn(ictx[j - 512]);
    else bv = __float2bfloat16_rn(ih[j - 1536]);
    d_xc0[idx] = bv;
    if (j < 1024) {
        d_xc1[n * 2048 + 1024 + j] = __float2bfloat16_rn(ih[1024 + j]);
        d_xc2[n * 2048 + 1024 + j] = __float2bfloat16_rn(ih[2048 + j]);
        d_cbuf[0][n * 1024 + j] = ic[j];
        d_cbuf[1][n * 1024 + j] = ic[1024 + j];
        d_cbuf[2][n * 1024 + j] = ic[2048 + j];
        d_h2[n * 1024 + j] = ih[2048 + j];
    }
}

__global__ void out0_kernel(float* __restrict__ out) {
    int idx = blockIdx.x * blockDim.x + threadIdx.x;
    if (idx < NB * VOC) {
        int n = idx / VOC, v = idx % VOC;
        out[(long)n * TT * VOC + v] = (v == 1) ? 10000.0f : 0.0f;
    }
}

// ---------------- fused LSTM: 256 thr, warps tile MxN, 5-stage pipeline ----------------
// grid 128 (jblk), CTA tile 64 batch x 32 permuted rows, chunk = 64 K-cols.
// stage: X 64x64 bf16 (row stride 144B) = 9216B + W 32x64 = 4608B -> 13824B, x5 stages.
#define LSTG 13824
#define LS_SMEM (5 * LSTG)

template <int LAYER>
__device__ __forceinline__ void lstm_ld(char* smem, int stg, int k0, int tid, int bn) {
    uint32_t st = smem_u32(smem) + stg * LSTG;
    const __nv_bfloat16* Xc = (LAYER == 0) ? d_xc0 : (LAYER == 1) ? d_xc1 : d_xc2;
    const __nv_bfloat16* Wc = (LAYER == 0) ? d_wcat0 : d_wcat12[LAYER - 1];
    const int Ktot = (LAYER == 0) ? 2560 : 2048;
#pragma unroll
    for (int i = 0; i < 2; i++) {
        int gI = tid + i * 256;
        int row = gI >> 3, c = gI & 7;
        CPA16(st + row * 144 + c * 16, Xc + (long)row * Ktot + k0 + c * 8);
    }
    {
        int row = tid >> 3, c = tid & 7;
        CPA16(st + 9216 + row * 144 + c * 16, Wc + ((long)bn * 32 + row) * Ktot + k0 + c * 8);
    }
}

template <int LAYER>
__global__ __launch_bounds__(256) void lstm_fused(int step) {
    extern __shared__ char smem[];
    __shared__ float sbias[32];
    const int Ktot = (LAYER == 0) ? 2560 : 2048;
    const int NCH = Ktot / 64;
    const int tid = threadIdx.x;
    const int w = tid >> 5, lane = tid & 31, g = lane >> 2, tig = lane & 3;
    const int bn = blockIdx.x;
    const int m0 = (w & 3) * 16, n0 = (w >> 2) * 16;

    if (tid < 32) sbias[tid] = d_bsum[LAYER][(tid & 3) * 1024 + bn * 8 + (tid >> 2)];

    float acc[2][4] = {};

    lstm_ld<LAYER>(smem, 0, 0, tid, bn);   CP_COMMIT();
    lstm_ld<LAYER>(smem, 1, 64, tid, bn);  CP_COMMIT();
    lstm_ld<LAYER>(smem, 2, 128, tid, bn); CP_COMMIT();
    lstm_ld<LAYER>(smem, 3, 192, tid, bn); CP_COMMIT();

    for (int c = 0; c < NCH; c++) {
        if (c < NCH - 3) CP_WAIT3();
        else if (c == NCH - 3) CP_WAIT2();
        else if (c == NCH - 2) CP_WAIT1();
        else CP_WAIT0();
        __syncthreads();
        if (c + 4 < NCH) {
            lstm_ld<LAYER>(smem, (c + 4) % 5, (c + 4) * 64, tid, bn);
            CP_COMMIT();
        }
        const uint32_t* Xu = (const uint32_t*)(smem + (c % 5) * LSTG);
        const uint32_t* Wu = Xu + 2304;
#pragma unroll
        for (int kk = 0; kk < 4; kk++) {
            uint32_t a[4];
            int ab = (m0 + g) * 36 + kk * 8 + tig;
            a[0] = Xu[ab]; a[1] = Xu[ab + 288]; a[2] = Xu[ab + 4]; a[3] = Xu[ab + 292];
#pragma unroll
            for (int nf = 0; nf < 2; nf++) {
                int nb = (n0 + nf * 8 + g) * 36 + kk * 8 + tig;
                mma_bf16(acc[nf], a, Wu[nb], Wu[nb + 4]);
            }
        }
    }

    // dump mma frags into an fp32 smem tile [64 batch][32 rows], stride 36 (reuse stage 0)
    __syncthreads();
    float* T = (float*)smem;
#pragma unroll
    for (int nf = 0; nf < 2; nf++) {
        int col = n0 + nf * 8 + tig * 2;
        T[(m0 + g) * 36 + col] = acc[nf][0];
        T[(m0 + g) * 36 + col + 1] = acc[nf][1];
        T[(m0 + g + 8) * 36 + col] = acc[nf][2];
        T[(m0 + g + 8) * 36 + col + 1] = acc[nf][3];
    }
    __syncthreads();

    // gate epilogue: 512 (n,j) cells, 2 per thread. row layout jr*4 + q.
#pragma unroll
    for (int u = 0; u < 2; u++) {
        int idx = tid * 2 + u;
        int n = idx >> 3, jr = idx & 7;
        int j = bn * 8 + jr;
        float iv = T[n * 36 + jr * 4 + 0] + sbias[jr * 4 + 0];
        float fv = T[n * 36 + jr * 4 + 1] + sbias[jr * 4 + 1];
        float gv = T[n * 36 + jr * 4 + 2] + sbias[jr * 4 + 2];
        float ov = T[n * 36 + jr * 4 + 3] + sbias[jr * 4 + 3];
        float c2 = sigmf(fv) * d_cbuf[LAYER][n * 1024 + j] + sigmf(iv) * tanhf(gv);
        float h2 = sigmf(ov) * tanhf(c2);
        d_cbuf[LAYER][n * 1024 + j] = c2;
        __nv_bfloat16 hb = __float2bfloat16_rn(h2);
        if (LAYER == 0) {
            d_xc1[n * 2048 + j] = hb;
            d_xc0[n * 2560 + 1536 + j] = hb;
        } else if (LAYER == 1) {
            d_xc2[n * 2048 + j] = hb;
            d_xc1[n * 2048 + 1024 + j] = hb;
        } else {
            d_xc2[n * 2048 + 1024 + j] = hb;
            d_h2[n * 1024 + j] = h2;
            d_hlastb[((long)step * NB + n) * 1024 + j] = hb;
        }
    }
}

// ---------------- attention part 1: energy = keys . h2 (bf16 keys) ----------------
__global__ void energy_kernel() {
    int n = blockIdx.x;
    int l = blockIdx.y * 8 + (threadIdx.x >> 5);
    int lane = threadIdx.x & 31;
    __shared__ float hs[DEC];
    for (int k = threadIdx.x; k < DEC; k += 256) hs[k] = d_h2[n * DEC + k];
    __syncthreads();
    if (l >= LL) return;
    const __nv_bfloat162* kr = (const __nv_bfloat162*)(d_kbf + ((long)n * LL + l) * DEC);
    float s = 0.f;
#pragma unroll
    for (int i = 0; i < 16; i++) {
        __nv_bfloat162 v = kr[lane + i * 32];
        int k2 = (lane + i * 32) * 2;
        s += __bfloat162float(v.x) * hs[k2] + __bfloat162float(v.y) * hs[k2 + 1];
    }
#pragma unroll
    for (int o = 16; o; o >>= 1) s += __shfl_xor_sync(0xffffffffu, s, o);
    if (lane == 0) d_att[n * LL + l] = s;
}

// ---------------- attention part 2: softmax + ctx + x0 build ----------------
__global__ void softctx_kernel(const int* __restrict__ captions, const float* __restrict__ emb,
                               int next_step) {
    int n = blockIdx.x;
    int tid = threadIdx.x;
    int wid = tid >> 5, lane = tid & 31;
    __shared__ float e[LL];
    __shared__ float red[8], red2[8];
    float v = (tid < LL) ? d_att[n * LL + tid] : -3.4e38f;
    float m = v;
#pragma unroll
    for (int o = 16; o; o >>= 1) m = fmaxf(m, __shfl_xor_sync(0xffffffffu, m, o));
    if (lane == 0) red[wid] = m;
    __syncthreads();
    if (tid < 8) {
        float mm = red[tid];
#pragma unroll
        for (int o = 4; o; o >>= 1) mm = fmaxf(mm, __shfl_xor_sync(0xffu, mm, o));
        if (tid == 0) red[0] = mm;
    }
    __syncthreads();
    float gm = red[0];
    float ex = (tid < LL) ? expf(v - gm) : 0.f;
    float s = ex;
#pragma unroll
    for (int o = 16; o; o >>= 1) s += __shfl_xor_sync(0xffffffffu, s, o);
    if (lane == 0) red2[wid] = s;
    __syncthreads();
    if (tid < 8) {
        float ss = red2[tid];
#pragma unroll
        for (int o = 4; o; o >>= 1) ss += __shfl_xor_sync(0xffu, ss, o);
        if (tid == 0) red2[0] = ss;
    }
    __syncthreads();
    if (tid < LL) e[tid] = ex / red2[0];
    __syncthreads();
    int col = blockIdx.y * 256 + tid;
    const __nv_bfloat16* vp = d_vbf + (long)n * LL * PROJD + col;
    float acc = 0.f;
#pragma unroll 4
    for (int l = 0; l < LL; l++) acc += e[l] * __bfloat162float(vp[(long)l * PROJD]);
    d_xc0[n * 2560 + 512 + col] = __float2bfloat16_rn(acc);
    if (blockIdx.y == 0) {
        int tok = captions[n * TT + next_step];
        for (int k = tid; k < EMB; k += 256)
            d_xc0[n * 2560 + k] = __float2bfloat16_rn(emb[(long)tok * EMB + k]);
    }
}

// ---------------- projection (bf16 mma, 4-stage): out = hlast @ out_W^T ----------------
#define PSTAGE 20480
#define PJ_SMEM (4 * PSTAGE)

__device__ __forceinline__ void proj_ld(uint32_t st, int bm, int bn, int k0, int tid) {
#pragma unroll
    for (int i = 0; i < 2; i++) {
        int gI = tid + i * 256;
        int row = gI >> 2, c = gI & 3;
        CPA16(st + row * 80 + c * 16, d_hlastb + (long)(bm * 128 + row) * DEC + k0 + c * 8);
    }
#pragma unroll
    for (int i = 0; i < 2; i++) {
        int gI = tid + i * 256;
        int row = gI >> 2, c = gI & 3;
        CPA16(st + 10240 + row * 80 + c * 16, d_pw + (long)(bn * 128 + row) * DEC + k0 + c * 8);
    }
}

__global__ __launch_bounds__(256) void proj_mma(const float* __restrict__ bias,
                                                float* __restrict__ out) {
    extern __shared__ char smem[];
    uint32_t sb = smem_u32(smem);
    const int tid = threadIdx.x;
    const int w = tid >> 5, lane = tid & 31, g = lane >> 2, tig = lane & 3;
    const int wm = w >> 2, wn = w & 3;
    const int bm = blockIdx.x, bn = blockIdx.y;

    float acc[4][4][4] = {};

    proj_ld(sb, bm, bn, 0, tid);  CP_COMMIT();
    proj_ld(sb + PSTAGE, bm, bn, 32, tid); CP_COMMIT();
    proj_ld(sb + 2 * PSTAGE, bm, bn, 64, tid); CP_COMMIT();

    for (int c = 0; c < 32; c++) {
        if (c + 2 < 32) CP_WAIT2();
        else if (c + 1 < 32) CP_WAIT1();
        else CP_WAIT0();
        __syncthreads();
        if (c + 3 < 32) { proj_ld(sb + ((c + 3) & 3) * PSTAGE, bm, bn, (c + 3) * 32, tid); CP_COMMIT(); }
        const uint32_t* Au = (const uint32_t*)(smem + (c & 3) * PSTAGE);
        const uint32_t* Bu = (const uint32_t*)(smem + (c & 3) * PSTAGE + 10240);
#pragma unroll
        for (int ks = 0; ks < 2; ks++) {
            int k8 = ks * 8;
            uint32_t a[4][4];
#pragma unroll
            for (int mi = 0; mi < 4; mi++) {
                int r = (wm * 64 + mi * 16 + g) * 20;
                a[mi][0] = Au[r + k8 + tig];
                a[mi][1] = Au[r + 160 + k8 + tig];
                a[mi][2] = Au[r + k8 + tig + 4];
                a[mi][3] = Au[r + 160 + k8 + tig + 4];
            }
#pragma unroll
            for (int nj = 0; nj < 4; nj++) {
                int nr = (wn * 32 + nj * 8 + g) * 20;
                uint32_t b0 = Bu[nr + k8 + tig], b1 = Bu[nr + k8 + tig + 4];
#pragma unroll
                for (int mi = 0; mi < 4; mi++) mma_bf16(acc[mi][nj], a[mi], b0, b1);
            }
        }
    }

#pragma unroll
    for (int mi = 0; mi < 4; mi++) {
#pragma unroll
        for (int nj = 0; nj < 4; nj++) {
            int m0 = bm * 128 + wm * 64 + mi * 16 + g;
            int vv = bn * 128 + wn * 32 + nj * 8 + tig * 2;
            float b0 = bias[vv], b1 = bias[vv + 1];
            {
                int step = m0 >> 6, nn = m0 & 63;
                *(float2*)(out + ((long)nn * TT + step + 1) * VOC + vv) =
                    make_float2(acc[mi][nj][0] + b0, acc[mi][nj][1] + b1);
            }
            {
                int m1 = m0 + 8;
                int step = m1 >> 6, nn = m1 & 63;
                *(float2*)(out + ((long)nn * TT + step + 1) * VOC + vv) =
                    make_float2(acc[mi][nj][2] + b0, acc[mi][nj][3] + b1);
            }
        }
    }
}

// ---------------- launch ----------------
extern "C" void kernel_launch(void* const* d_in, const int* in_sizes, int n_in,
                              void* d_out, int out_size) {
    int sh = (n_in >= 19) ? 0 : 1;
    const float* keys     = (const float*)d_in[0];
    const float* values   = (const float*)d_in[1];
    const int*   captions = (const int*)d_in[3];
    const float* emb      = (const float*)d_in[5 - sh];
    const float* W_ih0    = (const float*)d_in[6 - sh];
    const float* W_hh0    = (const float*)d_in[7 - sh];
    const float* b_ih0    = (const float*)d_in[8 - sh];
    const float* b_hh0    = (const float*)d_in[9 - sh];
    const float* W_ih_r   = (const float*)d_in[10 - sh];
    const float* W_hh_r   = (const float*)d_in[11 - sh];
    const float* b_ih_r   = (const float*)d_in[12 - sh];
    const float* b_hh_r   = (const float*)d_in[13 - sh];
    const float* out_W    = (const float*)d_in[14 - sh];
    const float* out_b    = (const float*)d_in[15 - sh];
    const float* init_h   = (const float*)d_in[16 - sh];
    const float* init_c   = (const float*)d_in[17 - sh];
    const float* init_ctx = (const float*)d_in[18 - sh];
    float* out = (float*)d_out;

    cudaFuncSetAttribute(lstm_fused<0>, cudaFuncAttributeMaxDynamicSharedMemorySize, LS_SMEM);
    cudaFuncSetAttribute(lstm_fused<1>, cudaFuncAttributeMaxDynamicSharedMemorySize, LS_SMEM);
    cudaFuncSetAttribute(lstm_fused<2>, cudaFuncAttributeMaxDynamicSharedMemorySize, LS_SMEM);
    cudaFuncSetAttribute(proj_mma, cudaFuncAttributeMaxDynamicSharedMemorySize, PJ_SMEM);

    conv_all<<<2048, 256>>>((const float4*)W_ih0, (const float4*)W_hh0,
                            (const float4*)W_ih_r, (const float4*)W_hh_r,
                            (const float4*)out_W, (const float4*)keys, (const float4*)values,
                            (const float4*)b_ih0, (const float4*)b_hh0,
                            (const float4*)b_ih_r, (const float4*)b_hh_r);

    init_state<<<640, 256>>>(init_h, init_c, init_ctx, emb);
    out0_kernel<<<(NB * VOC + 255) / 256, 256>>>(out);

    for (int s = 0; s < NSTEP; s++) {
        lstm_fused<0><<<128, 256, LS_SMEM>>>(s);
        lstm_fused<1><<<128, 256, LS_SMEM>>>(s);
        lstm_fused<2><<<128, 256, LS_SMEM>>>(s);
        energy_kernel<<<dim3(64, 25), 256>>>();
        softctx_kernel<<<dim3(64, 4), 256>>>(captions, emb, s + 1);
    }

    proj_mma<<<dim3(12, 250), 256, PJ_SMEM>>>(out_b, out);
}

// round 11
// speedup vs baseline: 1.3394x; 1.1199x over previous
#include <cuda_runtime.h>
#include <cuda_bf16.h>
#include <stdint.h>

#define NB 64
#define TT 25
#define LL 196
#define VOC 32000
#define EMB 512
#define PROJD 1024
#define DEC 1024
#define NSTEP 24

// ---------------- device state (no allocations allowed) ----------------
// Weights bf16, GATE-PERMUTED rows: permuted row p = jblk*32 + jr*4 + q
// (j = jblk*8+jr, gate q in {i,f,g,o}) <-> original row q*1024 + j.
__device__ __nv_bfloat16 d_wcat0[4096 * 2560];      // layer0 [Wih | Whh]
__device__ __nv_bfloat16 d_wcat12[2][4096 * 2048];  // layers 1,2
__device__ __nv_bfloat16 d_pw[(long)VOC * DEC];     // out_W bf16
__device__ __nv_bfloat16 d_kbf[(long)NB * LL * DEC];
__device__ __nv_bfloat16 d_vbf[(long)NB * LL * PROJD];
__device__ float d_bsum[3][4096];                   // b_ih + b_hh (original order)
__device__ __nv_bfloat16 d_xc0[NB * 2560];          // [emb | ctx | h0]
__device__ __nv_bfloat16 d_xc1[NB * 2048];          // [h0_new | h1]
__device__ __nv_bfloat16 d_xc2[NB * 2048];          // [h1_new | h2]
__device__ __nv_bfloat16 d_hlastb[(long)NSTEP * NB * DEC];
__device__ float d_cbuf[3][NB * DEC];
__device__ float d_h2[NB * DEC];
__device__ float d_att[NB * LL];

__device__ __forceinline__ float sigmf(float x) { return 1.0f / (1.0f + expf(-x)); }

__device__ __forceinline__ uint32_t smem_u32(const void* p) {
    uint32_t a;
    asm("{ .reg .u64 t; cvta.to.shared.u64 t, %1; cvt.u32.u64 %0, t; }" : "=r"(a) : "l"(p));
    return a;
}
#define CPA16(d, s) asm volatile("cp.async.ca.shared.global [%0], [%1], 16;" :: "r"(d), "l"(s))
#define CP_COMMIT() asm volatile("cp.async.commit_group;" ::: "memory")
#define CP_WAIT(n) asm volatile("cp.async.wait_group %0;" :: "n"(n) : "memory")

#define LDSM4(r0, r1, r2, r3, addr) \
    asm volatile("ldmatrix.sync.aligned.m8n8.x4.shared.b16 {%0,%1,%2,%3}, [%4];" \
                 : "=r"(r0), "=r"(r1), "=r"(r2), "=r"(r3) : "r"(addr))

// C[16x8] += A[16x16] * B[16x8], bf16 inputs, fp32 accum
__device__ __forceinline__ void mma_bf16(float* c, const uint32_t* a, uint32_t b0, uint32_t b1) {
    asm volatile(
        "mma.sync.aligned.m16n8k16.row.col.f32.bf16.bf16.f32 "
        "{%0,%1,%2,%3}, {%4,%5,%6,%7}, {%8,%9}, {%0,%1,%2,%3};"
        : "+f"(c[0]), "+f"(c[1]), "+f"(c[2]), "+f"(c[3])
        : "r"(a[0]), "r"(a[1]), "r"(a[2]), "r"(a[3]), "r"(b0), "r"(b1));
}

// ---------------- single fused conversion kernel ----------------
__global__ void conv_all(const float4* __restrict__ Wih0, const float4* __restrict__ Whh0,
                         const float4* __restrict__ Wihr, const float4* __restrict__ Whhr,
                         const float4* __restrict__ outW, const float4* __restrict__ keys,
                         const float4* __restrict__ values,
                         const float4* __restrict__ bih0, const float4* __restrict__ bhh0,
                         const float4* __restrict__ bihr, const float4* __restrict__ bhhr) {
    const long N0 = 2621440L;            // w0: 4096 x 640 granules
    const long N1 = N0 + 2097152L;       // w1
    const long N2 = N1 + 2097152L;       // w2
    const long N3 = N2 + 8192000L;       // pw
    const long N4 = N3 + 3211264L;       // keys
    const long N5 = N4 + 3211264L;       // values
    const long N6 = N5 + 3072L;          // biases
    for (long i = (long)blockIdx.x * blockDim.x + threadIdx.x; i < N6;
         i += (long)gridDim.x * blockDim.x) {
        float4 v;
        __nv_bfloat16* dst;
        if (i < N0) {
            long o = i;
            int p = (int)(o / 640), k4 = (int)(o - (long)p * 640);
            int r = (p & 3) * 1024 + (p >> 5) * 8 + ((p >> 2) & 7);
            v = (k4 < 384) ? Wih0[(long)r * 384 + k4] : Whh0[(long)r * 256 + (k4 - 384)];
            dst = d_wcat0 + o * 4;
        } else if (i < N2) {
            int lay = (i < N1) ? 0 : 1;
            long o = i - (lay ? N1 : N0);
            int p = (int)(o / 512), k4 = (int)(o - (long)p * 512);
            int r = (p & 3) * 1024 + (p >> 5) * 8 + ((p >> 2) & 7) + lay * 4096;
            v = (k4 < 256) ? Wihr[(long)r * 256 + k4] : Whhr[(long)r * 256 + (k4 - 256)];
            dst = d_wcat12[lay] + o * 4;
        } else if (i < N3) {
            long o = i - N2; v = outW[o]; dst = d_pw + o * 4;
        } else if (i < N4) {
            long o = i - N3; v = keys[o]; dst = d_kbf + o * 4;
        } else if (i < N5) {
            long o = i - N4; v = values[o]; dst = d_vbf + o * 4;
        } else {
            long o = i - N5;
            int lay = (int)(o >> 10), r4 = (int)(o & 1023);
            float4 a, b;
            if (lay == 0)      { a = bih0[r4];        b = bhh0[r4]; }
            else if (lay == 1) { a = bihr[r4];        b = bhhr[r4]; }
            else               { a = bihr[1024 + r4]; b = bhhr[1024 + r4]; }
            *(float4*)&d_bsum[lay][r4 * 4] =
                make_float4(a.x + b.x, a.y + b.y, a.z + b.z, a.w + b.w);
            continue;
        }
        __nv_bfloat162* d2 = (__nv_bfloat162*)dst;
        d2[0] = __nv_bfloat162(__float2bfloat16_rn(v.x), __float2bfloat16_rn(v.y));
        d2[1] = __nv_bfloat162(__float2bfloat16_rn(v.z), __float2bfloat16_rn(v.w));
    }
}

// ---------------- init ----------------
__global__ void init_state(const float* __restrict__ ih, const float* __restrict__ ic,
                           const float* __restrict__ ictx, const float* __restrict__ emb) {
    int idx = blockIdx.x * blockDim.x + threadIdx.x;
    if (idx >= NB * 2560) return;
    int n = idx / 2560, j = idx % 2560;
    __nv_bfloat16 bv;
    if (j < 512) bv = __float2bfloat16_rn(emb[512 + j]);  // <start> = token 1
    else if (j < 1536) bv = __float2bfloat16_rn(ictx[j - 512]);
    else bv = __float2bfloat16_rn(ih[j - 1536]);
    d_xc0[idx] = bv;
    if (j < 1024) {
        d_xc1[n * 2048 + 1024 + j] = __float2bfloat16_rn(ih[1024 + j]);
        d_xc2[n * 2048 + 1024 + j] = __float2bfloat16_rn(ih[2048 + j]);
        d_cbuf[0][n * 1024 + j] = ic[j];
        d_cbuf[1][n * 1024 + j] = ic[1024 + j];
        d_cbuf[2][n * 1024 + j] = ic[2048 + j];
        d_h2[n * 1024 + j] = ih[2048 + j];
    }
}

__global__ void out0_kernel(float* __restrict__ out) {
    int idx = blockIdx.x * blockDim.x + threadIdx.x;
    if (idx < NB * VOC) {
        int n = idx / VOC, v = idx % VOC;
        out[(long)n * TT * VOC + v] = (v == 1) ? 10000.0f : 0.0f;
    }
}

// ---------------- fused LSTM: 256 thr, 10-stage pipeline, ldmatrix fragments ----------------
// grid 128 (jblk), CTA tile 64 batch x 32 permuted rows, chunk = 64 K-cols.
// stage: X 64x64 bf16 (row stride 144B) = 9216B + W 32x64 = 4608B -> 13824B, x10 stages.
#define LSTG 13824
#define LS_NST 10
#define LS_SMEM (LS_NST * LSTG)

template <int LAYER>
__device__ __forceinline__ void lstm_ld(char* smem, int stg, int k0, int tid, int bn) {
    uint32_t st = smem_u32(smem) + stg * LSTG;
    const __nv_bfloat16* Xc = (LAYER == 0) ? d_xc0 : (LAYER == 1) ? d_xc1 : d_xc2;
    const __nv_bfloat16* Wc = (LAYER == 0) ? d_wcat0 : d_wcat12[LAYER - 1];
    const int Ktot = (LAYER == 0) ? 2560 : 2048;
#pragma unroll
    for (int i = 0; i < 2; i++) {
        int gI = tid + i * 256;
        int row = gI >> 3, c = gI & 7;
        CPA16(st + row * 144 + c * 16, Xc + (long)row * Ktot + k0 + c * 8);
    }
    {
        int row = tid >> 3, c = tid & 7;
        CPA16(st + 9216 + row * 144 + c * 16, Wc + ((long)bn * 32 + row) * Ktot + k0 + c * 8);
    }
}

template <int LAYER>
__global__ __launch_bounds__(256) void lstm_fused(int step) {
    extern __shared__ char smem[];
    __shared__ float sbias[32];
    const int Ktot = (LAYER == 0) ? 2560 : 2048;
    const int NCH = Ktot / 64;
    const int tid = threadIdx.x;
    const int w = tid >> 5, lane = tid & 31, g = lane >> 2, tig = lane & 3;
    const int bn = blockIdx.x;
    const int m0 = (w & 3) * 16, n0 = (w >> 2) * 16;
    const uint32_t sbase = smem_u32(smem);

    if (tid < 32) sbias[tid] = d_bsum[LAYER][(tid & 3) * 1024 + bn * 8 + (tid >> 2)];

    float acc[2][4] = {};

    // ldmatrix per-thread address offsets (within a stage)
    const uint32_t a_off =
        (uint32_t)((m0 + (lane & 7) + ((lane >> 3) & 1) * 8) * 144 + (lane >> 4) * 16);
    const uint32_t b_off =
        (uint32_t)(9216 + (n0 + (lane & 7) + ((lane >> 4) & 1) * 8) * 144 +
                   ((lane >> 3) & 1) * 16);

#pragma unroll
    for (int i = 0; i < 9; i++) {
        lstm_ld<LAYER>(smem, i, i * 64, tid, bn);
        CP_COMMIT();
    }

    for (int c = 0; c < NCH; c++) {
        int d = NCH - 1 - c;
        if (d >= 8) CP_WAIT(8);
        else if (d == 7) CP_WAIT(7);
        else if (d == 6) CP_WAIT(6);
        else if (d == 5) CP_WAIT(5);
        else if (d == 4) CP_WAIT(4);
        else if (d == 3) CP_WAIT(3);
        else if (d == 2) CP_WAIT(2);
        else if (d == 1) CP_WAIT(1);
        else CP_WAIT(0);
        __syncthreads();
        if (c + 9 < NCH) {
            lstm_ld<LAYER>(smem, (c + 9) % LS_NST, (c + 9) * 64, tid, bn);
            CP_COMMIT();
        }
        uint32_t xb = sbase + (c % LS_NST) * LSTG;
#pragma unroll
        for (int kk = 0; kk < 4; kk++) {
            uint32_t a[4], b[4];
            LDSM4(a[0], a[1], a[2], a[3], xb + a_off + kk * 32);
            LDSM4(b[0], b[1], b[2], b[3], xb + b_off + kk * 32);
            mma_bf16(acc[0], a, b[0], b[1]);
            mma_bf16(acc[1], a, b[2], b[3]);
        }
    }

    // dump mma frags into fp32 smem tile [64 batch][32 rows], stride 36 (reuse stage 0)
    __syncthreads();
    float* T = (float*)smem;
#pragma unroll
    for (int nf = 0; nf < 2; nf++) {
        int col = n0 + nf * 8 + tig * 2;
        T[(m0 + g) * 36 + col] = acc[nf][0];
        T[(m0 + g) * 36 + col + 1] = acc[nf][1];
        T[(m0 + g + 8) * 36 + col] = acc[nf][2];
        T[(m0 + g + 8) * 36 + col + 1] = acc[nf][3];
    }
    __syncthreads();

    // gate epilogue: 512 (n,j) cells, 2 per thread. row layout jr*4 + q.
#pragma unroll
    for (int u = 0; u < 2; u++) {
        int idx = tid * 2 + u;
        int n = idx >> 3, jr = idx & 7;
        int j = bn * 8 + jr;
        float iv = T[n * 36 + jr * 4 + 0] + sbias[jr * 4 + 0];
        float fv = T[n * 36 + jr * 4 + 1] + sbias[jr * 4 + 1];
        float gv = T[n * 36 + jr * 4 + 2] + sbias[jr * 4 + 2];
        float ov = T[n * 36 + jr * 4 + 3] + sbias[jr * 4 + 3];
        float c2 = sigmf(fv) * d_cbuf[LAYER][n * 1024 + j] + sigmf(iv) * tanhf(gv);
        float h2 = sigmf(ov) * tanhf(c2);
        d_cbuf[LAYER][n * 1024 + j] = c2;
        __nv_bfloat16 hb = __float2bfloat16_rn(h2);
        if (LAYER == 0) {
            d_xc1[n * 2048 + j] = hb;
            d_xc0[n * 2560 + 1536 + j] = hb;
        } else if (LAYER == 1) {
            d_xc2[n * 2048 + j] = hb;
            d_xc1[n * 2048 + 1024 + j] = hb;
        } else {
            d_xc2[n * 2048 + 1024 + j] = hb;
            d_h2[n * 1024 + j] = h2;
            d_hlastb[((long)step * NB + n) * 1024 + j] = hb;
        }
    }
}

// ---------------- attention part 1: energy = keys . h2 (bf16 keys) ----------------
__global__ void energy_kernel() {
    int n = blockIdx.x;
    int l = blockIdx.y * 8 + (threadIdx.x >> 5);
    int lane = threadIdx.x & 31;
    __shared__ float hs[DEC];
    for (int k = threadIdx.x; k < DEC; k += 256) hs[k] = d_h2[n * DEC + k];
    __syncthreads();
    if (l >= LL) return;
    const __nv_bfloat162* kr = (const __nv_bfloat162*)(d_kbf + ((long)n * LL + l) * DEC);
    float s = 0.f;
#pragma unroll
    for (int i = 0; i < 16; i++) {
        __nv_bfloat162 v = kr[lane + i * 32];
        int k2 = (lane + i * 32) * 2;
        s += __bfloat162float(v.x) * hs[k2] + __bfloat162float(v.y) * hs[k2 + 1];
    }
#pragma unroll
    for (int o = 16; o; o >>= 1) s += __shfl_xor_sync(0xffffffffu, s, o);
    if (lane == 0) d_att[n * LL + l] = s;
}

// ---------------- attention part 2: softmax + ctx + x0 build ----------------
__global__ void softctx_kernel(const int* __restrict__ captions, const float* __restrict__ emb,
                               int next_step) {
    int n = blockIdx.x;
    int tid = threadIdx.x;
    int wid = tid >> 5, lane = tid & 31;
    __shared__ float e[LL];
    __shared__ float red[8], red2[8];
    float v = (tid < LL) ? d_att[n * LL + tid] : -3.4e38f;
    float m = v;
#pragma unroll
    for (int o = 16; o; o >>= 1) m = fmaxf(m, __shfl_xor_sync(0xffffffffu, m, o));
    if (lane == 0) red[wid] = m;
    __syncthreads();
    if (tid < 8) {
        float mm = red[tid];
#pragma unroll
        for (int o = 4; o; o >>= 1) mm = fmaxf(mm, __shfl_xor_sync(0xffu, mm, o));
        if (tid == 0) red[0] = mm;
    }
    __syncthreads();
    float gm = red[0];
    float ex = (tid < LL) ? expf(v - gm) : 0.f;
    float s = ex;
#pragma unroll
    for (int o = 16; o; o >>= 1) s += __shfl_xor_sync(0xffffffffu, s, o);
    if (lane == 0) red2[wid] = s;
    __syncthreads();
    if (tid < 8) {
        float ss = red2[tid];
#pragma unroll
        for (int o = 4; o; o >>= 1) ss += __shfl_xor_sync(0xffu, ss, o);
        if (tid == 0) red2[0] = ss;
    }
    __syncthreads();
    if (tid < LL) e[tid] = ex / red2[0];
    __syncthreads();
    int col = blockIdx.y * 256 + tid;
    const __nv_bfloat16* vp = d_vbf + (long)n * LL * PROJD + col;
    float acc = 0.f;
#pragma unroll 4
    for (int l = 0; l < LL; l++) acc += e[l] * __bfloat162float(vp[(long)l * PROJD]);
    d_xc0[n * 2560 + 512 + col] = __float2bfloat16_rn(acc);
    if (blockIdx.y == 0) {
        int tok = captions[n * TT + next_step];
        for (int k = tid; k < EMB; k += 256)
            d_xc0[n * 2560 + k] = __float2bfloat16_rn(emb[(long)tok * EMB + k]);
    }
}

// ---------------- projection (bf16 mma, 4-stage): out = hlast @ out_W^T ----------------
#define PSTAGE 20480
#define PJ_SMEM (4 * PSTAGE)

__device__ __forceinline__ void proj_ld(uint32_t st, int bm, int bn, int k0, int tid) {
#pragma unroll
    for (int i = 0; i < 2; i++) {
        int gI = tid + i * 256;
        int row = gI >> 2, c = gI & 3;
        CPA16(st + row * 80 + c * 16, d_hlastb + (long)(bm * 128 + row) * DEC + k0 + c * 8);
    }
#pragma unroll
    for (int i = 0; i < 2; i++) {
        int gI = tid + i * 256;
        int row = gI >> 2, c = gI & 3;
        CPA16(st + 10240 + row * 80 + c * 16, d_pw + (long)(bn * 128 + row) * DEC + k0 + c * 8);
    }
}

__global__ __launch_bounds__(256) void proj_mma(const float* __restrict__ bias,
                                                float* __restrict__ out) {
    extern __shared__ char smem[];
    uint32_t sb = smem_u32(smem);
    const int tid = threadIdx.x;
    const int w = tid >> 5, lane = tid & 31, g = lane >> 2, tig = lane & 3;
    const int wm = w >> 2, wn = w & 3;
    const int bm = blockIdx.x, bn = blockIdx.y;

    float acc[4][4][4] = {};

    proj_ld(sb, bm, bn, 0, tid);  CP_COMMIT();
    proj_ld(sb + PSTAGE, bm, bn, 32, tid); CP_COMMIT();
    proj_ld(sb + 2 * PSTAGE, bm, bn, 64, tid); CP_COMMIT();

    for (int c = 0; c < 32; c++) {
        if (c + 2 < 32) CP_WAIT(2);
        else if (c + 1 < 32) CP_WAIT(1);
        else CP_WAIT(0);
        __syncthreads();
        if (c + 3 < 32) { proj_ld(sb + ((c + 3) & 3) * PSTAGE, bm, bn, (c + 3) * 32, tid); CP_COMMIT(); }
        const uint32_t* Au = (const uint32_t*)(smem + (c & 3) * PSTAGE);
        const uint32_t* Bu = (const uint32_t*)(smem + (c & 3) * PSTAGE + 10240);
#pragma unroll
        for (int ks = 0; ks < 2; ks++) {
            int k8 = ks * 8;
            uint32_t a[4][4];
#pragma unroll
            for (int mi = 0; mi < 4; mi++) {
                int r = (wm * 64 + mi * 16 + g) * 20;
                a[mi][0] = Au[r + k8 + tig];
                a[mi][1] = Au[r + 160 + k8 + tig];
                a[mi][2] = Au[r + k8 + tig + 4];
                a[mi][3] = Au[r + 160 + k8 + tig + 4];
            }
#pragma unroll
            for (int nj = 0; nj < 4; nj++) {
                int nr = (wn * 32 + nj * 8 + g) * 20;
                uint32_t b0 = Bu[nr + k8 + tig], b1 = Bu[nr + k8 + tig + 4];
#pragma unroll
                for (int mi = 0; mi < 4; mi++) mma_bf16(acc[mi][nj], a[mi], b0, b1);
            }
        }
    }

#pragma unroll
    for (int mi = 0; mi < 4; mi++) {
#pragma unroll
        for (int nj = 0; nj < 4; nj++) {
            int m0 = bm * 128 + wm * 64 + mi * 16 + g;
            int vv = bn * 128 + wn * 32 + nj * 8 + tig * 2;
            float b0 = bias[vv], b1 = bias[vv + 1];
            {
                int step = m0 >> 6, nn = m0 & 63;
                *(float2*)(out + ((long)nn * TT + step + 1) * VOC + vv) =
                    make_float2(acc[mi][nj][0] + b0, acc[mi][nj][1] + b1);
            }
            {
                int m1 = m0 + 8;
                int step = m1 >> 6, nn = m1 & 63;
                *(float2*)(out + ((long)nn * TT + step + 1) * VOC + vv) =
                    make_float2(acc[mi][nj][2] + b0, acc[mi][nj][3] + b1);
            }
        }
    }
}

// ---------------- launch ----------------
extern "C" void kernel_launch(void* const* d_in, const int* in_sizes, int n_in,
                              void* d_out, int out_size) {
    int sh = (n_in >= 19) ? 0 : 1;
    const float* keys     = (const float*)d_in[0];
    const float* values   = (const float*)d_in[1];
    const int*   captions = (const int*)d_in[3];
    const float* emb      = (const float*)d_in[5 - sh];
    const float* W_ih0    = (const float*)d_in[6 - sh];
    const float* W_hh0    = (const float*)d_in[7 - sh];
    const float* b_ih0    = (const float*)d_in[8 - sh];
    const float* b_hh0    = (const float*)d_in[9 - sh];
    const float* W_ih_r   = (const float*)d_in[10 - sh];
    const float* W_hh_r   = (const float*)d_in[11 - sh];
    const float* b_ih_r   = (const float*)d_in[12 - sh];
    const float* b_hh_r   = (const float*)d_in[13 - sh];
    const float* out_W    = (const float*)d_in[14 - sh];
    const float* out_b    = (const float*)d_in[15 - sh];
    const float* init_h   = (const float*)d_in[16 - sh];
    const float* init_c   = (const float*)d_in[17 - sh];
    const float* init_ctx = (const float*)d_in[18 - sh];
    float* out = (float*)d_out;

    cudaFuncSetAttribute(lstm_fused<0>, cudaFuncAttributeMaxDynamicSharedMemorySize, LS_SMEM);
    cudaFuncSetAttribute(lstm_fused<1>, cudaFuncAttributeMaxDynamicSharedMemorySize, LS_SMEM);
    cudaFuncSetAttribute(lstm_fused<2>, cudaFuncAttributeMaxDynamicSharedMemorySize, LS_SMEM);
    cudaFuncSetAttribute(proj_mma, cudaFuncAttributeMaxDynamicSharedMemorySize, PJ_SMEM);

    conv_all<<<2048, 256>>>((const float4*)W_ih0, (const float4*)W_hh0,
                            (const float4*)W_ih_r, (const float4*)W_hh_r,
                            (const float4*)out_W, (const float4*)keys, (const float4*)values,
                            (const float4*)b_ih0, (const float4*)b_hh0,
                            (const float4*)b_ih_r, (const float4*)b_hh_r);

    init_state<<<640, 256>>>(init_h, init_c, init_ctx, emb);
    out0_kernel<<<(NB * VOC + 255) / 256, 256>>>(out);

    for (int s = 0; s < NSTEP; s++) {
        lstm_fused<0><<<128, 256, LS_SMEM>>>(s);
        lstm_fused<1><<<128, 256, LS_SMEM>>>(s);
        lstm_fused<2><<<128, 256, LS_SMEM>>>(s);
        energy_kernel<<<dim3(64, 25), 256>>>();
        softctx_kernel<<<dim3(64, 4), 256>>>(captions, emb, s + 1);
    }

    proj_mma<<<dim3(12, 250), 256, PJ_SMEM>>>(out_b, out);
}